// round 1
// baseline (speedup 1.0000x reference)
#include <cuda_runtime.h>
#include <math.h>

#define BB 2
#define NHH 12
#define TT 2048
#define DD 768
#define NN 256
#define KFLAT (NHH * NN)   // 3072

#define INV2PI 0.15915494309189535f
#define TWOPI  6.283185307179586f

// ---------------- scratch (device globals: allocation-free) ----------------
__device__ float g_xs  [(size_t)BB * NHH * TT * NN];   // x_sparse  (b,h,t,n)
__device__ float g_qr  [(size_t)BB * NHH * TT * NN];   // QR == KR  (b,h,t,n)
__device__ float g_sc  [(size_t)BB * NHH * TT * TT];   // masked scores (b,h,t,s)
__device__ float g_ykv [(size_t)BB * NHH * TT * DD];   // yKV, layernormed in place
__device__ float g_flat[(size_t)BB * TT * NHH * NN];   // xy in (b,t,h,n) for MLP
__device__ float g_ymlp[(size_t)BB * TT * DD];

// ---------------- 128x128x8 fp32 tiled GEMM core ----------------
// A: row-major MxK (k contiguous), pre-offset to tile row 0.
// B: if BTRANS -> row-major NxK (k contiguous), pre-offset to tile col-row 0
//    else      -> k-major KxN (n contiguous), pre-offset to tile col 0.
template <bool BTRANS>
__device__ __forceinline__ void gemm128_core(
    const float* __restrict__ A, int lda,
    const float* __restrict__ B, int ldb,
    int K, float acc[8][8])
{
    __shared__ float As[8][128];
    __shared__ float Bs[8][128];

    const int tid  = threadIdx.x;
    const int tx   = tid & 15;
    const int ty   = tid >> 4;
    const int arow = tid >> 1;          // 0..127
    const int ak4  = (tid & 1) * 4;     // 0 or 4
    const int bdk  = tid >> 5;          // 0..7  (direct B)
    const int bdn  = (tid & 31) * 4;    // 0..124

    for (int k0 = 0; k0 < K; k0 += 8) {
        float4 av = *reinterpret_cast<const float4*>(A + (size_t)arow * lda + k0 + ak4);
        As[ak4 + 0][arow] = av.x;
        As[ak4 + 1][arow] = av.y;
        As[ak4 + 2][arow] = av.z;
        As[ak4 + 3][arow] = av.w;
        if (BTRANS) {
            float4 bv = *reinterpret_cast<const float4*>(B + (size_t)arow * ldb + k0 + ak4);
            Bs[ak4 + 0][arow] = bv.x;
            Bs[ak4 + 1][arow] = bv.y;
            Bs[ak4 + 2][arow] = bv.z;
            Bs[ak4 + 3][arow] = bv.w;
        } else {
            *reinterpret_cast<float4*>(&Bs[bdk][bdn]) =
                *reinterpret_cast<const float4*>(B + (size_t)(k0 + bdk) * ldb + bdn);
        }
        __syncthreads();
#pragma unroll
        for (int kk = 0; kk < 8; ++kk) {
            float a[8], b[8];
#pragma unroll
            for (int i = 0; i < 8; ++i) a[i] = As[kk][ty * 8 + i];
#pragma unroll
            for (int j = 0; j < 8; ++j) b[j] = Bs[kk][tx * 8 + j];
#pragma unroll
            for (int i = 0; i < 8; ++i)
#pragma unroll
                for (int j = 0; j < 8; ++j)
                    acc[i][j] = fmaf(a[i], b[j], acc[i][j]);
        }
        __syncthreads();
    }
}

// ---------------- block-wide sum (256 threads) ----------------
__device__ __forceinline__ float blockSum(float v)
{
    __shared__ float sh[9];
    const int lane = threadIdx.x & 31;
    const int w    = threadIdx.x >> 5;
#pragma unroll
    for (int o = 16; o > 0; o >>= 1) v += __shfl_down_sync(0xffffffffu, v, o);
    __syncthreads();
    if (lane == 0) sh[w] = v;
    __syncthreads();
    if (threadIdx.x == 0) {
        float s = 0.f;
#pragma unroll
        for (int i = 0; i < 8; ++i) s += sh[i];
        sh[8] = s;
    }
    __syncthreads();
    return sh[8];
}

// ---------------- kernel 1: latent = relu(x @ enc_h), rope -> QR ----------------
__global__ __launch_bounds__(256)
void k_latent(const float* __restrict__ x, const float* __restrict__ enc)
{
    const int h = blockIdx.z;
    float acc[8][8] = {};
    const float* A  = x   + (size_t)blockIdx.y * 128 * DD;
    const float* Bm = enc + (size_t)h * DD * NN + blockIdx.x * 128;
    gemm128_core<false>(A, DD, Bm, NN, DD, acc);

    const int tx = threadIdx.x & 15, ty = threadIdx.x >> 4;
    const int r0 = blockIdx.y * 128 + ty * 8;
    const int n0 = blockIdx.x * 128 + tx * 8;
#pragma unroll
    for (int i = 0; i < 8; ++i) {
        const int r = r0 + i;
        const int b = r / TT, t = r % TT;
        const size_t base = ((size_t)(b * NHH + h) * TT + t) * NN;
        const float tf = (float)t;
#pragma unroll
        for (int j = 0; j < 8; j += 2) {
            const int n = n0 + j;                       // even
            float ve = fmaxf(acc[i][j],     0.f);
            float vo = fmaxf(acc[i][j + 1], 0.f);
            g_xs[base + n]     = ve;
            g_xs[base + n + 1] = vo;
            // freq = THETA^{-q/N} / (2pi),  THETA = 2^16, q = n (even) -> 2^{-n/16}
            float freq = exp2f(-(float)n * (1.0f / 16.0f)) * INV2PI;
            float ph   = fmodf(tf * freq, 1.0f) * TWOPI;
            float c, s;
            sincosf(ph, &s, &c);
            g_qr[base + n]     = ve * c - vo * s;
            g_qr[base + n + 1] = vo * c + ve * s;
        }
    }
}

// ---------------- kernel 2: scores = (QR QR^T) * strict-lower mask ----------------
__global__ __launch_bounds__(256)
void k_scores()
{
    const int sb = blockIdx.x, tb = blockIdx.y, bh = blockIdx.z;
    if (sb > tb) return;                     // above block-diagonal: never computed/read
    const float* base = g_qr + (size_t)bh * TT * NN;
    float acc[8][8] = {};
    gemm128_core<true>(base + (size_t)tb * 128 * NN, NN,
                       base + (size_t)sb * 128 * NN, NN, NN, acc);

    const int tx = threadIdx.x & 15, ty = threadIdx.x >> 4;
    const int t0 = tb * 128 + ty * 8;
    const int s0 = sb * 128 + tx * 8;
    float* out = g_sc + (size_t)bh * TT * TT;
#pragma unroll
    for (int i = 0; i < 8; ++i) {
        const int t = t0 + i;
#pragma unroll
        for (int j = 0; j < 8; ++j) {
            const int s = s0 + j;
            out[(size_t)t * TT + s] = (s < t) ? acc[i][j] : 0.f;
        }
    }
}

// ---------------- kernel 3: yKV = scores @ x_b  (triangular K) ----------------
__global__ __launch_bounds__(256)
void k_ykv(const float* __restrict__ x)
{
    const int db = blockIdx.x, tb = blockIdx.y, bh = blockIdx.z;
    const int b  = bh / NHH;
    float acc[8][8] = {};
    const float* A  = g_sc + (size_t)bh * TT * TT + (size_t)tb * 128 * TT;
    const float* Bm = x + (size_t)b * TT * DD + db * 128;
    const int K = (tb + 1) * 128;            // strict-lower: no s >= (tb+1)*128 contributes
    gemm128_core<false>(A, TT, Bm, DD, K, acc);

    const int tx = threadIdx.x & 15, ty = threadIdx.x >> 4;
    const int t0 = tb * 128 + ty * 8;
    const int d0 = db * 128 + tx * 8;
#pragma unroll
    for (int i = 0; i < 8; ++i) {
        const size_t row = ((size_t)bh * TT + (t0 + i)) * DD;
#pragma unroll
        for (int j = 0; j < 8; ++j)
            g_ykv[row + d0 + j] = acc[i][j];
    }
}

// ---------------- kernel 4: in-place layernorm of yKV rows (len 768) ----------------
__global__ __launch_bounds__(256)
void k_ln_ykv()
{
    const size_t row = blockIdx.x;
    float* p = g_ykv + row * DD;
    const int tid = threadIdx.x;
    float v[3];
    float sum = 0.f;
#pragma unroll
    for (int i = 0; i < 3; ++i) { v[i] = p[tid + 256 * i]; sum += v[i]; }
    const float m = blockSum(sum) * (1.0f / DD);
    float sq = 0.f;
#pragma unroll
    for (int i = 0; i < 3; ++i) { float d = v[i] - m; sq += d * d; }
    const float rstd = rsqrtf(blockSum(sq) * (1.0f / DD) + 1e-5f);
#pragma unroll
    for (int i = 0; i < 3; ++i) p[tid + 256 * i] = (v[i] - m) * rstd;
}

// ---------------- kernel 5: y_sparse = relu(yKVn @ encv_h); xy = x_sparse*y_sparse ----------------
__global__ __launch_bounds__(256)
void k_ysparse(const float* __restrict__ encv, float* __restrict__ out_xy)
{
    const int nb = blockIdx.x, tb = blockIdx.y, bh = blockIdx.z;
    const int b = bh / NHH, h = bh % NHH;
    float acc[8][8] = {};
    const float* A  = g_ykv + (size_t)bh * TT * DD + (size_t)tb * 128 * DD;
    const float* Bm = encv + (size_t)h * DD * NN + nb * 128;
    gemm128_core<false>(A, DD, Bm, NN, DD, acc);

    const int tx = threadIdx.x & 15, ty = threadIdx.x >> 4;
    const int t0 = tb * 128 + ty * 8;
    const int n0 = nb * 128 + tx * 8;
#pragma unroll
    for (int i = 0; i < 8; ++i) {
        const int t = t0 + i;
        const size_t sbase = ((size_t)bh * TT + t) * NN;
        const size_t fbase = (((size_t)b * TT + t) * NHH + h) * NN;
#pragma unroll
        for (int j = 0; j < 8; ++j) {
            const int n = n0 + j;
            float xy = fmaxf(acc[i][j], 0.f) * g_xs[sbase + n];
            out_xy[sbase + n] = xy;     // output #2, layout (b,h,t,n)
            g_flat[fbase + n] = xy;     // (b,t,h,n) for the MLP GEMM
        }
    }
}

// ---------------- kernel 6: yMLP = flat @ decoder ----------------
__global__ __launch_bounds__(256)
void k_ymlp(const float* __restrict__ dec)
{
    float acc[8][8] = {};
    const float* A  = g_flat + (size_t)blockIdx.y * 128 * KFLAT;
    const float* Bm = dec + blockIdx.x * 128;
    gemm128_core<false>(A, KFLAT, Bm, DD, KFLAT, acc);

    const int tx = threadIdx.x & 15, ty = threadIdx.x >> 4;
    const int r0 = blockIdx.y * 128 + ty * 8;
    const int d0 = blockIdx.x * 128 + tx * 8;
#pragma unroll
    for (int i = 0; i < 8; ++i) {
        float* row = g_ymlp + (size_t)(r0 + i) * DD;
#pragma unroll
        for (int j = 0; j < 8; ++j)
            row[d0 + j] = acc[i][j];
    }
}

// ---------------- kernel 7: ln(yMLP) * sqrt(reg) * scale; out = ln(x + y) ----------------
__global__ __launch_bounds__(256)
void k_final(const float* __restrict__ x, const float* __restrict__ scale,
             const float* __restrict__ ract, float* __restrict__ out)
{
    const size_t r = blockIdx.x;          // b*T + t
    const int tid = threadIdx.x;
    const float* yp = g_ymlp + r * DD;
    const float* xp = x + r * DD;

    float v[3];
    float sum = 0.f;
#pragma unroll
    for (int i = 0; i < 3; ++i) { v[i] = yp[tid + 256 * i]; sum += v[i]; }
    const float m1 = blockSum(sum) * (1.0f / DD);
    float sq = 0.f;
#pragma unroll
    for (int i = 0; i < 3; ++i) { float d = v[i] - m1; sq += d * d; }
    const float rs1 = rsqrtf(blockSum(sq) * (1.0f / DD) + 1e-5f);

    float z[3];
    float sum2 = 0.f;
#pragma unroll
    for (int i = 0; i < 3; ++i) {
        const int d = tid + 256 * i;
        float y = (v[i] - m1) * rs1;
        y *= sqrtf(0.1f / (ract[d] + 1e-6f)) * scale[d];
        z[i] = xp[d] + y;
        sum2 += z[i];
    }
    const float m2 = blockSum(sum2) * (1.0f / DD);
    float sq2 = 0.f;
#pragma unroll
    for (int i = 0; i < 3; ++i) { float d = z[i] - m2; sq2 += d * d; }
    const float rs2 = rsqrtf(blockSum(sq2) * (1.0f / DD) + 1e-5f);
#pragma unroll
    for (int i = 0; i < 3; ++i)
        out[r * DD + tid + 256 * i] = (z[i] - m2) * rs2;
}

// ---------------- launch ----------------
extern "C" void kernel_launch(void* const* d_in, const int* in_sizes, int n_in,
                              void* d_out, int out_size)
{
    const float* x     = (const float*)d_in[0];
    const float* enc   = (const float*)d_in[1];
    const float* encv  = (const float*)d_in[2];
    const float* dec   = (const float*)d_in[3];
    const float* scale = (const float*)d_in[4];
    const float* ract  = (const float*)d_in[5];

    float* out    = (float*)d_out;
    float* out_xy = out + (size_t)BB * TT * DD;   // second tuple element

    // 1) x_latent -> relu -> x_sparse; rope -> QR
    k_latent<<<dim3(NN / 128, (BB * TT) / 128, NHH), 256>>>(x, enc);
    // 2) scores = QR QR^T, strict-lower masked, block-triangular launch
    k_scores<<<dim3(TT / 128, TT / 128, BB * NHH), 256>>>();
    // 3) yKV = scores @ x
    k_ykv<<<dim3(DD / 128, TT / 128, BB * NHH), 256>>>(x);
    // 4) layernorm(yKV) in place
    k_ln_ykv<<<BB * NHH * TT, 256>>>();
    // 5) y_sparse, xy_sparse (writes output #2 + flat copy)
    k_ysparse<<<dim3(NN / 128, TT / 128, BB * NHH), 256>>>(encv, out_xy);
    // 6) yMLP = flat @ decoder
    k_ymlp<<<dim3(DD / 128, (BB * TT) / 128), 256>>>(dec);
    // 7) final double layernorm + regulation -> output #1
    k_final<<<BB * TT, 256>>>(x, scale, ract, out);
}

// round 4
// speedup vs baseline: 2.8100x; 2.8100x over previous
#include <cuda_runtime.h>
#include <cuda_bf16.h>
#include <math.h>
#include <stdint.h>

#define BB 2
#define NHH 12
#define TT 2048
#define DD 768
#define NN 256
#define KFLAT (NHH * NN)   // 3072

#define INV2PI 0.15915494309189535f
#define TWOPI  6.283185307179586f

typedef __nv_bfloat16 bf16;

// ---------------- device-global scratch (allocation-free) ----------------
__device__ float g_xs  [(size_t)BB * NHH * TT * NN];   // x_sparse fp32
__device__ float g_ykv [(size_t)BB * NHH * TT * DD];   // yKV fp32 (pre-LN)
__device__ float g_ymlp[(size_t)BB * TT * DD];

// bf16 hi/lo operand planes
__device__ bf16 g_xa_h [(size_t)BB * TT * DD],        g_xa_l [(size_t)BB * TT * DD];        // x rows [bt][d]
__device__ bf16 g_xt_h [(size_t)BB * DD * TT],        g_xt_l [(size_t)BB * DD * TT];        // x^T [b][d][t]
__device__ bf16 g_ep_h [(size_t)NHH * NN * DD],       g_ep_l [(size_t)NHH * NN * DD];       // enc  [h][n][d]
__device__ bf16 g_evp_h[(size_t)NHH * NN * DD],       g_evp_l[(size_t)NHH * NN * DD];       // encv [h][n][d]
__device__ bf16 g_dt_h [(size_t)DD * KFLAT],          g_dt_l [(size_t)DD * KFLAT];          // dec^T [d][hn]
__device__ bf16 g_qr_h [(size_t)BB * NHH * TT * NN],  g_qr_l [(size_t)BB * NHH * TT * NN];  // QR [bh][t][n]
__device__ bf16 g_sc_h [(size_t)BB * NHH * TT * TT],  g_sc_l [(size_t)BB * NHH * TT * TT];  // scores [bh][t][s]
__device__ bf16 g_yn_h [(size_t)BB * NHH * TT * DD],  g_yn_l [(size_t)BB * NHH * TT * DD];  // LN(yKV) [bh][t][d]
__device__ bf16 g_fl_h [(size_t)BB * TT * KFLAT],     g_fl_l [(size_t)BB * TT * KFLAT];     // xy flat [bt][hn]

// ---------------- SMEM layout: per buffer: Ah(10240) Al Bh Bl ----------------
#define PLANE 10240          // 128 rows * 80 B (32 bf16 + 8 pad)
#define BUFSZ (4 * PLANE)    // 40960
#define SMEM_BYTES (2 * BUFSZ)

// ---------------- low-level helpers ----------------
__device__ __forceinline__ uint32_t smem_u32(const void* p) {
    uint32_t a;
    asm("{ .reg .u64 t; cvta.to.shared.u64 t, %1; cvt.u32.u64 %0, t; }" : "=r"(a) : "l"(p));
    return a;
}
__device__ __forceinline__ void cp16(uint32_t dst, const void* src) {
    asm volatile("cp.async.cg.shared.global [%0], [%1], 16;"
                 :: "r"(dst), "l"(__cvta_generic_to_global(src)) : "memory");
}
__device__ __forceinline__ void cp_commit() {
    asm volatile("cp.async.commit_group;" ::: "memory");
}
template <int N>
__device__ __forceinline__ void cp_wait() {
    asm volatile("cp.async.wait_group %0;" :: "n"(N) : "memory");
}
__device__ __forceinline__ void ldsm4(uint32_t* r, uint32_t addr) {
    asm volatile("ldmatrix.sync.aligned.m8n8.x4.shared.b16 {%0,%1,%2,%3}, [%4];"
                 : "=r"(r[0]), "=r"(r[1]), "=r"(r[2]), "=r"(r[3]) : "r"(addr));
}
__device__ __forceinline__ void mma_bf16(float* c, const uint32_t* a, const uint32_t* b) {
    asm volatile("mma.sync.aligned.m16n8k16.row.col.f32.bf16.bf16.f32 "
                 "{%0,%1,%2,%3}, {%4,%5,%6,%7}, {%8,%9}, {%0,%1,%2,%3};"
                 : "+f"(c[0]), "+f"(c[1]), "+f"(c[2]), "+f"(c[3])
                 : "r"(a[0]), "r"(a[1]), "r"(a[2]), "r"(a[3]), "r"(b[0]), "r"(b[1]));
}

__device__ __forceinline__ void store_split1(bf16* hp, bf16* lp, float v) {
    bf16 h = __float2bfloat16(v);
    *hp = h;
    *lp = __float2bfloat16(v - __bfloat162float(h));
}
__device__ __forceinline__ void store_split2(bf16* hp, bf16* lp, float v0, float v1) {
    __nv_bfloat162 h = __floats2bfloat162_rn(v0, v1);
    __nv_bfloat162 l = __floats2bfloat162_rn(v0 - __bfloat162float(h.x),
                                             v1 - __bfloat162float(h.y));
    *reinterpret_cast<__nv_bfloat162*>(hp) = h;
    *reinterpret_cast<__nv_bfloat162*>(lp) = l;
}

// ---------------- slab loader: A[128 x 32], B[128 x 32], hi+lo ----------------
__device__ __forceinline__ void issue_slab(
    uint32_t sb,
    const bf16* __restrict__ Ah, const bf16* __restrict__ Al, int lda,
    const bf16* __restrict__ Bh, const bf16* __restrict__ Bl, int ldb, int k0)
{
    const int tid = threadIdx.x;
#pragma unroll
    for (int i = 0; i < 2; ++i) {
        const int idx = tid + 256 * i;
        const int row = idx >> 2;
        const int seg = idx & 3;
        const uint32_t so = row * 80 + seg * 16;
        const size_t go = (size_t)row;
        const int eo = k0 + seg * 8;
        cp16(sb + so,             Ah + go * lda + eo);
        cp16(sb + PLANE + so,     Al + go * lda + eo);
        cp16(sb + 2 * PLANE + so, Bh + go * ldb + eo);
        cp16(sb + 3 * PLANE + so, Bl + go * ldb + eo);
    }
}

// ---------------- slab compute: 2 k16-steps x 3 split terms ----------------
__device__ __forceinline__ void compute_slab(uint32_t sb, float acc[4][4][4])
{
    const int lane = threadIdx.x & 31, wid = threadIdx.x >> 5;
    const int wm = wid >> 2, wn = wid & 3;
    const uint32_t aoff = (uint32_t)(wm * 64 + (lane & 15)) * 80 + (((lane >> 4) & 1) << 4);
    const uint32_t boff = (uint32_t)(wn * 32 + ((lane >> 4) & 1) * 8 + (lane & 7)) * 80
                        + (((lane >> 3) & 1) << 4);
#pragma unroll
    for (int kk = 0; kk < 2; ++kk) {
        const uint32_t ak = sb + aoff + kk * 32;
        const uint32_t bk = sb + 2 * PLANE + boff + kk * 32;
        uint32_t Ah[4][4], Al[4][4], Bh[2][4], Bl[2][4];
#pragma unroll
        for (int mi = 0; mi < 4; ++mi) ldsm4(Ah[mi], ak + mi * 1280);
#pragma unroll
        for (int p = 0; p < 2; ++p) ldsm4(Bh[p], bk + p * 1280);
#pragma unroll
        for (int mi = 0; mi < 4; ++mi)
#pragma unroll
            for (int ni = 0; ni < 4; ++ni)
                mma_bf16(acc[mi][ni], Ah[mi], &Bh[ni >> 1][(ni & 1) * 2]);
#pragma unroll
        for (int p = 0; p < 2; ++p) ldsm4(Bl[p], bk + PLANE + p * 1280);
#pragma unroll
        for (int mi = 0; mi < 4; ++mi)
#pragma unroll
            for (int ni = 0; ni < 4; ++ni)
                mma_bf16(acc[mi][ni], Ah[mi], &Bl[ni >> 1][(ni & 1) * 2]);
#pragma unroll
        for (int mi = 0; mi < 4; ++mi) ldsm4(Al[mi], ak + PLANE + mi * 1280);
#pragma unroll
        for (int mi = 0; mi < 4; ++mi)
#pragma unroll
            for (int ni = 0; ni < 4; ++ni)
                mma_bf16(acc[mi][ni], Al[mi], &Bh[ni >> 1][(ni & 1) * 2]);
    }
}

// ---------------- GEMM driver: acc[128x128] += split(A) @ split(B)^T ----------------
__device__ __forceinline__ void gemm_main(
    uint32_t smbase,
    const bf16* __restrict__ Ah, const bf16* __restrict__ Al, int lda,
    const bf16* __restrict__ Bh, const bf16* __restrict__ Bl, int ldb,
    int K, float acc[4][4][4])
{
    const int ns = K >> 5;
    issue_slab(smbase, Ah, Al, lda, Bh, Bl, ldb, 0);
    cp_commit();
    for (int s = 0; s < ns; ++s) {
        if (s + 1 < ns) {
            issue_slab(smbase + ((s + 1) & 1) * BUFSZ, Ah, Al, lda, Bh, Bl, ldb, (s + 1) * 32);
            cp_commit();
            cp_wait<1>();
        } else {
            cp_wait<0>();
        }
        __syncthreads();
        compute_slab(smbase + (s & 1) * BUFSZ, acc);
        __syncthreads();
    }
}

// Epilogue iteration: calls f(r_loc, c_loc, v0, v1) for each accum pair
template <typename F>
__device__ __forceinline__ void epilog_foreach(float acc[4][4][4], F f)
{
    const int lane = threadIdx.x & 31, wid = threadIdx.x >> 5;
    const int wm = wid >> 2, wn = wid & 3;
#pragma unroll
    for (int mi = 0; mi < 4; ++mi)
#pragma unroll
        for (int ni = 0; ni < 4; ++ni)
#pragma unroll
            for (int hf = 0; hf < 2; ++hf) {
                const int r_loc = wm * 64 + mi * 16 + (lane >> 2) + hf * 8;
                const int c_loc = wn * 32 + ni * 8 + (lane & 3) * 2;
                f(r_loc, c_loc, acc[mi][ni][hf * 2], acc[mi][ni][hf * 2 + 1]);
            }
}

// ---------------- conversion kernels (once per launch, cheap) ----------------
__global__ __launch_bounds__(256)
void k_split(const float* __restrict__ in, bf16* __restrict__ hp, bf16* __restrict__ lp, int n)
{
    for (int i = blockIdx.x * 256 + threadIdx.x; i < n; i += gridDim.x * 256)
        store_split1(hp + i, lp + i, in[i]);
}

// in [z][R][C] fp32 -> out [z][C][R] bf16 hi/lo
__global__ __launch_bounds__(256)
void k_tsplit(const float* __restrict__ in, bf16* __restrict__ hp, bf16* __restrict__ lp,
              int R, int C)
{
    __shared__ float tile[32][33];
    const int z = blockIdx.z;
    const int r0 = blockIdx.y * 32, c0 = blockIdx.x * 32;
    const int tx = threadIdx.x & 31, ty = threadIdx.x >> 5;   // 32 x 8
    const float* src = in + (size_t)z * R * C;
#pragma unroll
    for (int i = 0; i < 32; i += 8)
        tile[ty + i][tx] = src[(size_t)(r0 + ty + i) * C + c0 + tx];
    __syncthreads();
    bf16* hdst = hp + (size_t)z * R * C;
    bf16* ldst = lp + (size_t)z * R * C;
#pragma unroll
    for (int i = 0; i < 32; i += 8) {
        const float v = tile[tx][ty + i];
        const size_t o = (size_t)(c0 + ty + i) * R + r0 + tx;
        store_split1(hdst + o, ldst + o, v);
    }
}

// ---------------- block-wide sum (256 threads) ----------------
__device__ __forceinline__ float blockSum(float v)
{
    __shared__ float sh[9];
    const int lane = threadIdx.x & 31;
    const int w    = threadIdx.x >> 5;
#pragma unroll
    for (int o = 16; o > 0; o >>= 1) v += __shfl_down_sync(0xffffffffu, v, o);
    __syncthreads();
    if (lane == 0) sh[w] = v;
    __syncthreads();
    if (threadIdx.x == 0) {
        float s = 0.f;
#pragma unroll
        for (int i = 0; i < 8; ++i) s += sh[i];
        sh[8] = s;
    }
    __syncthreads();
    return sh[8];
}

// ---------------- kernel 1: latent = relu(x @ enc_h); rope -> QR planes ----------------
__global__ __launch_bounds__(256)
void k_latent()
{
    extern __shared__ char sm[];
    const uint32_t smb = smem_u32(sm);
    const int h = blockIdx.z;
    const int by = blockIdx.y, bx = blockIdx.x;
    float acc[4][4][4] = {};
    gemm_main(smb,
              g_xa_h + (size_t)by * 128 * DD,
              g_xa_l + (size_t)by * 128 * DD, DD,
              g_ep_h + ((size_t)h * NN + bx * 128) * DD,
              g_ep_l + ((size_t)h * NN + bx * 128) * DD, DD,
              DD, acc);

    epilog_foreach(acc, [&](int r_loc, int c_loc, float v0, float v1) {
        const int r = by * 128 + r_loc;
        const int b = r >> 11, t = r & 2047;
        const int n = bx * 128 + c_loc;          // even
        const size_t base = ((size_t)(b * NHH + h) * TT + t) * NN + n;
        const float e = fmaxf(v0, 0.f), o = fmaxf(v1, 0.f);
        *reinterpret_cast<float2*>(g_xs + base) = make_float2(e, o);
        const float freq = exp2f(-(float)n * 0.0625f) * INV2PI;
        const float ph = fmodf((float)t * freq, 1.0f) * TWOPI;
        float c, s;
        sincosf(ph, &s, &c);
        store_split2(g_qr_h + base, g_qr_l + base, e * c - o * s, o * c + e * s);
    });
}

// ---------------- kernel 2: scores = (QR QR^T) * strict-lower mask ----------------
__global__ __launch_bounds__(256)
void k_scores()
{
    const int sb = blockIdx.x, tb = blockIdx.y, bh = blockIdx.z;
    if (sb > tb) return;
    extern __shared__ char sm[];
    const uint32_t smb = smem_u32(sm);
    float acc[4][4][4] = {};
    gemm_main(smb,
              g_qr_h + ((size_t)bh * TT + tb * 128) * NN,
              g_qr_l + ((size_t)bh * TT + tb * 128) * NN, NN,
              g_qr_h + ((size_t)bh * TT + sb * 128) * NN,
              g_qr_l + ((size_t)bh * TT + sb * 128) * NN, NN,
              NN, acc);

    epilog_foreach(acc, [&](int r_loc, int c_loc, float v0, float v1) {
        const int t = tb * 128 + r_loc;
        const int s = sb * 128 + c_loc;
        const size_t o = (size_t)bh * TT * TT + (size_t)t * TT + s;
        store_split2(g_sc_h + o, g_sc_l + o,
                     (s < t) ? v0 : 0.f, (s + 1 < t) ? v1 : 0.f);
    });
}

// ---------------- kernel 3: yKV = scores @ x_b (triangular K) ----------------
__global__ __launch_bounds__(256)
void k_ykv()
{
    extern __shared__ char sm[];
    const uint32_t smb = smem_u32(sm);
    const int nb = blockIdx.x, tb = blockIdx.y, bh = blockIdx.z;
    const int b = bh / NHH;
    float acc[4][4][4] = {};
    gemm_main(smb,
              g_sc_h + (size_t)bh * TT * TT + (size_t)tb * 128 * TT,
              g_sc_l + (size_t)bh * TT * TT + (size_t)tb * 128 * TT, TT,
              g_xt_h + ((size_t)b * DD + nb * 128) * TT,
              g_xt_l + ((size_t)b * DD + nb * 128) * TT, TT,
              (tb + 1) * 128, acc);

    epilog_foreach(acc, [&](int r_loc, int c_loc, float v0, float v1) {
        const int t = tb * 128 + r_loc;
        const int d = nb * 128 + c_loc;
        *reinterpret_cast<float2*>(g_ykv + ((size_t)bh * TT + t) * DD + d) =
            make_float2(v0, v1);
    });
}

// ---------------- kernel 4: LN(yKV) -> bf16 planes ----------------
__global__ __launch_bounds__(256)
void k_ln_ykv()
{
    const size_t row = blockIdx.x;
    const float* p = g_ykv + row * DD;
    const int tid = threadIdx.x;
    float v[3];
    float sum = 0.f;
#pragma unroll
    for (int i = 0; i < 3; ++i) { v[i] = p[tid + 256 * i]; sum += v[i]; }
    const float m = blockSum(sum) * (1.0f / DD);
    float sq = 0.f;
#pragma unroll
    for (int i = 0; i < 3; ++i) { float d = v[i] - m; sq += d * d; }
    const float rstd = rsqrtf(blockSum(sq) * (1.0f / DD) + 1e-5f);
#pragma unroll
    for (int i = 0; i < 3; ++i) {
        const size_t o = row * DD + tid + 256 * i;
        store_split1(g_yn_h + o, g_yn_l + o, (v[i] - m) * rstd);
    }
}

// ---------------- kernel 5: y_sparse = relu(yn @ encv); xy = xs*ys ----------------
__global__ __launch_bounds__(256)
void k_ysparse(float* __restrict__ out_xy)
{
    extern __shared__ char sm[];
    const uint32_t smb = smem_u32(sm);
    const int nb = blockIdx.x, tb = blockIdx.y, bh = blockIdx.z;
    const int b = bh / NHH, h = bh % NHH;
    float acc[4][4][4] = {};
    gemm_main(smb,
              g_yn_h + ((size_t)bh * TT + tb * 128) * DD,
              g_yn_l + ((size_t)bh * TT + tb * 128) * DD, DD,
              g_evp_h + ((size_t)h * NN + nb * 128) * DD,
              g_evp_l + ((size_t)h * NN + nb * 128) * DD, DD,
              DD, acc);

    epilog_foreach(acc, [&](int r_loc, int c_loc, float v0, float v1) {
        const int t = tb * 128 + r_loc;
        const int n = nb * 128 + c_loc;
        const size_t sidx = ((size_t)bh * TT + t) * NN + n;
        const float2 xv = *reinterpret_cast<const float2*>(g_xs + sidx);
        const float xy0 = fmaxf(v0, 0.f) * xv.x;
        const float xy1 = fmaxf(v1, 0.f) * xv.y;
        *reinterpret_cast<float2*>(out_xy + sidx) = make_float2(xy0, xy1);
        const size_t fidx = ((size_t)(b * TT + t)) * KFLAT + h * NN + n;
        store_split2(g_fl_h + fidx, g_fl_l + fidx, xy0, xy1);
    });
}

// ---------------- kernel 6: yMLP = flat @ decoder ----------------
__global__ __launch_bounds__(256)
void k_ymlp()
{
    extern __shared__ char sm[];
    const uint32_t smb = smem_u32(sm);
    const int nb = blockIdx.x, by = blockIdx.y;
    float acc[4][4][4] = {};
    gemm_main(smb,
              g_fl_h + (size_t)by * 128 * KFLAT,
              g_fl_l + (size_t)by * 128 * KFLAT, KFLAT,
              g_dt_h + (size_t)nb * 128 * KFLAT,
              g_dt_l + (size_t)nb * 128 * KFLAT, KFLAT,
              KFLAT, acc);

    epilog_foreach(acc, [&](int r_loc, int c_loc, float v0, float v1) {
        const int r = by * 128 + r_loc;
        const int d = nb * 128 + c_loc;
        *reinterpret_cast<float2*>(g_ymlp + (size_t)r * DD + d) = make_float2(v0, v1);
    });
}

// ---------------- kernel 7: ln(yMLP)*sqrt(reg)*scale; out = ln(x+y) ----------------
__global__ __launch_bounds__(256)
void k_final(const float* __restrict__ x, const float* __restrict__ scale,
             const float* __restrict__ ract, float* __restrict__ out)
{
    const size_t r = blockIdx.x;
    const int tid = threadIdx.x;
    const float* yp = g_ymlp + r * DD;
    const float* xp = x + r * DD;

    float v[3];
    float sum = 0.f;
#pragma unroll
    for (int i = 0; i < 3; ++i) { v[i] = yp[tid + 256 * i]; sum += v[i]; }
    const float m1 = blockSum(sum) * (1.0f / DD);
    float sq = 0.f;
#pragma unroll
    for (int i = 0; i < 3; ++i) { float d = v[i] - m1; sq += d * d; }
    const float rs1 = rsqrtf(blockSum(sq) * (1.0f / DD) + 1e-5f);

    float z[3];
    float sum2 = 0.f;
#pragma unroll
    for (int i = 0; i < 3; ++i) {
        const int d = tid + 256 * i;
        float y = (v[i] - m1) * rs1;
        y *= sqrtf(0.1f / (ract[d] + 1e-6f)) * scale[d];
        z[i] = xp[d] + y;
        sum2 += z[i];
    }
    const float m2 = blockSum(sum2) * (1.0f / DD);
    float sq2 = 0.f;
#pragma unroll
    for (int i = 0; i < 3; ++i) { float d = z[i] - m2; sq2 += d * d; }
    const float rs2 = rsqrtf(blockSum(sq2) * (1.0f / DD) + 1e-5f);
#pragma unroll
    for (int i = 0; i < 3; ++i)
        out[r * DD + tid + 256 * i] = (z[i] - m2) * rs2;
}

// ---------------- launch ----------------
extern "C" void kernel_launch(void* const* d_in, const int* in_sizes, int n_in,
                              void* d_out, int out_size)
{
    const float* x     = (const float*)d_in[0];
    const float* enc   = (const float*)d_in[1];
    const float* encv  = (const float*)d_in[2];
    const float* dec   = (const float*)d_in[3];
    const float* scale = (const float*)d_in[4];
    const float* ract  = (const float*)d_in[5];

    float* out    = (float*)d_out;
    float* out_xy = out + (size_t)BB * TT * DD;

    static bool attr_done = false;
    if (!attr_done) {
        cudaFuncSetAttribute(k_latent,  cudaFuncAttributeMaxDynamicSharedMemorySize, SMEM_BYTES);
        cudaFuncSetAttribute(k_scores,  cudaFuncAttributeMaxDynamicSharedMemorySize, SMEM_BYTES);
        cudaFuncSetAttribute(k_ykv,     cudaFuncAttributeMaxDynamicSharedMemorySize, SMEM_BYTES);
        cudaFuncSetAttribute(k_ysparse, cudaFuncAttributeMaxDynamicSharedMemorySize, SMEM_BYTES);
        cudaFuncSetAttribute(k_ymlp,    cudaFuncAttributeMaxDynamicSharedMemorySize, SMEM_BYTES);
        attr_done = true;
    }

    bf16 *xa_h, *xa_l, *xt_h, *xt_l, *ep_h, *ep_l, *evp_h, *evp_l, *dt_h, *dt_l;
    cudaGetSymbolAddress((void**)&xa_h,  g_xa_h);  cudaGetSymbolAddress((void**)&xa_l,  g_xa_l);
    cudaGetSymbolAddress((void**)&xt_h,  g_xt_h);  cudaGetSymbolAddress((void**)&xt_l,  g_xt_l);
    cudaGetSymbolAddress((void**)&ep_h,  g_ep_h);  cudaGetSymbolAddress((void**)&ep_l,  g_ep_l);
    cudaGetSymbolAddress((void**)&evp_h, g_evp_h); cudaGetSymbolAddress((void**)&evp_l, g_evp_l);
    cudaGetSymbolAddress((void**)&dt_h,  g_dt_h);  cudaGetSymbolAddress((void**)&dt_l,  g_dt_l);

    // operand preparation
    k_split <<<4096, 256>>>(x, xa_h, xa_l, BB * TT * DD);
    k_tsplit<<<dim3(DD / 32, TT / 32, BB), 256>>>(x,    xt_h,  xt_l,  TT, DD);     // [b][T][D] -> [b][D][T]
    k_tsplit<<<dim3(NN / 32, DD / 32, NHH), 256>>>(enc,  ep_h,  ep_l,  DD, NN);    // [h][D][N] -> [h][N][D]
    k_tsplit<<<dim3(NN / 32, DD / 32, NHH), 256>>>(encv, evp_h, evp_l, DD, NN);
    k_tsplit<<<dim3(DD / 32, KFLAT / 32, 1), 256>>>(dec, dt_h,  dt_l,  KFLAT, DD); // [HN][D] -> [D][HN]

    // pipeline
    k_latent <<<dim3(2, 32, NHH),       256, SMEM_BYTES>>>();
    k_scores <<<dim3(16, 16, BB * NHH), 256, SMEM_BYTES>>>();
    k_ykv    <<<dim3(6, 16, BB * NHH),  256, SMEM_BYTES>>>();
    k_ln_ykv <<<BB * NHH * TT, 256>>>();
    k_ysparse<<<dim3(2, 16, BB * NHH),  256, SMEM_BYTES>>>(out_xy);
    k_ymlp   <<<dim3(6, 32),            256, SMEM_BYTES>>>();
    k_final  <<<BB * TT, 256>>>(x, scale, ract, out);
}

// round 5
// speedup vs baseline: 3.3730x; 1.2003x over previous
#include <cuda_runtime.h>
#include <cuda_bf16.h>
#include <math.h>
#include <stdint.h>

#define BB 2
#define NHH 12
#define TT 2048
#define DD 768
#define NN 256
#define KFLAT (NHH * NN)   // 3072
#define NCH 16             // chunks of 128 along T

#define INV2PI 0.15915494309189535f
#define TWOPI  6.283185307179586f

typedef __nv_bfloat16 bf16;

// ---------------- device-global scratch (allocation-free) ----------------
__device__ float g_xs  [(size_t)BB * NHH * TT * NN];   // x_sparse fp32
__device__ float g_ykv [(size_t)BB * NHH * TT * DD];   // yKV fp32 (pre-LN)
__device__ float g_ymlp[(size_t)BB * TT * DD];
__device__ float g_qrf [(size_t)BB * NHH * TT * NN];   // QR fp32 (for transpose)
__device__ float g_pst [(size_t)BB * NHH * NCH * DD * NN];  // P_i fp32 [bh][i][d][n]

// bf16 hi/lo operand planes
__device__ bf16 g_xa_h [(size_t)BB * TT * DD],        g_xa_l [(size_t)BB * TT * DD];        // x rows [bt][d]
__device__ bf16 g_xt_h [(size_t)BB * DD * TT],        g_xt_l [(size_t)BB * DD * TT];        // x^T [b][d][t]
__device__ bf16 g_ep_h [(size_t)NHH * NN * DD],       g_ep_l [(size_t)NHH * NN * DD];       // enc  [h][n][d]
__device__ bf16 g_evp_h[(size_t)NHH * NN * DD],       g_evp_l[(size_t)NHH * NN * DD];       // encv [h][n][d]
__device__ bf16 g_dt_h [(size_t)DD * KFLAT],          g_dt_l [(size_t)DD * KFLAT];          // dec^T [d][hn]
__device__ bf16 g_qr_h [(size_t)BB * NHH * TT * NN],  g_qr_l [(size_t)BB * NHH * TT * NN];  // QR [bh][t][n]
__device__ bf16 g_qrt_h[(size_t)BB * NHH * NN * TT],  g_qrt_l[(size_t)BB * NHH * NN * TT];  // QR^T [bh][n][t]
__device__ bf16 g_scd_h[(size_t)BB * NHH * NCH * 128 * 128],
                g_scd_l[(size_t)BB * NHH * NCH * 128 * 128];                                // diag score tiles
__device__ bf16 g_st_h [(size_t)BB * NHH * NCH * DD * NN],
                g_st_l [(size_t)BB * NHH * NCH * DD * NN];                                  // states [bh][i][d][n]
__device__ bf16 g_yn_h [(size_t)BB * NHH * TT * DD],  g_yn_l [(size_t)BB * NHH * TT * DD];  // LN(yKV) [bh][t][d]
__device__ bf16 g_fl_h [(size_t)BB * TT * KFLAT],     g_fl_l [(size_t)BB * TT * KFLAT];     // xy flat [bt][hn]

// ---------------- SMEM layout: per buffer: Ah(10240) Al Bh Bl ----------------
#define PLANE 10240          // 128 rows * 80 B (32 bf16 + 8 pad)
#define BUFSZ (4 * PLANE)    // 40960
#define SMEM_BYTES (2 * BUFSZ)

// ---------------- low-level helpers ----------------
__device__ __forceinline__ uint32_t smem_u32(const void* p) {
    uint32_t a;
    asm("{ .reg .u64 t; cvta.to.shared.u64 t, %1; cvt.u32.u64 %0, t; }" : "=r"(a) : "l"(p));
    return a;
}
__device__ __forceinline__ void cp16(uint32_t dst, const void* src) {
    asm volatile("cp.async.cg.shared.global [%0], [%1], 16;"
                 :: "r"(dst), "l"(__cvta_generic_to_global(src)) : "memory");
}
__device__ __forceinline__ void cp_commit() {
    asm volatile("cp.async.commit_group;" ::: "memory");
}
template <int N>
__device__ __forceinline__ void cp_wait() {
    asm volatile("cp.async.wait_group %0;" :: "n"(N) : "memory");
}
__device__ __forceinline__ void ldsm4(uint32_t* r, uint32_t addr) {
    asm volatile("ldmatrix.sync.aligned.m8n8.x4.shared.b16 {%0,%1,%2,%3}, [%4];"
                 : "=r"(r[0]), "=r"(r[1]), "=r"(r[2]), "=r"(r[3]) : "r"(addr));
}
__device__ __forceinline__ void mma_bf16(float* c, const uint32_t* a, const uint32_t* b) {
    asm volatile("mma.sync.aligned.m16n8k16.row.col.f32.bf16.bf16.f32 "
                 "{%0,%1,%2,%3}, {%4,%5,%6,%7}, {%8,%9}, {%0,%1,%2,%3};"
                 : "+f"(c[0]), "+f"(c[1]), "+f"(c[2]), "+f"(c[3])
                 : "r"(a[0]), "r"(a[1]), "r"(a[2]), "r"(a[3]), "r"(b[0]), "r"(b[1]));
}

__device__ __forceinline__ void store_split1(bf16* hp, bf16* lp, float v) {
    bf16 h = __float2bfloat16(v);
    *hp = h;
    *lp = __float2bfloat16(v - __bfloat162float(h));
}
__device__ __forceinline__ void store_split2(bf16* hp, bf16* lp, float v0, float v1) {
    __nv_bfloat162 h = __floats2bfloat162_rn(v0, v1);
    __nv_bfloat162 l = __floats2bfloat162_rn(v0 - __bfloat162float(h.x),
                                             v1 - __bfloat162float(h.y));
    *reinterpret_cast<__nv_bfloat162*>(hp) = h;
    *reinterpret_cast<__nv_bfloat162*>(lp) = l;
}

// ---------------- slab loader: A[128 x 32], B[128 x 32], hi+lo ----------------
__device__ __forceinline__ void issue_slab(
    uint32_t sb,
    const bf16* __restrict__ Ah, const bf16* __restrict__ Al, int lda,
    const bf16* __restrict__ Bh, const bf16* __restrict__ Bl, int ldb, int k0)
{
    const int tid = threadIdx.x;
#pragma unroll
    for (int i = 0; i < 2; ++i) {
        const int idx = tid + 256 * i;
        const int row = idx >> 2;
        const int seg = idx & 3;
        const uint32_t so = row * 80 + seg * 16;
        const size_t go = (size_t)row;
        const int eo = k0 + seg * 8;
        cp16(sb + so,             Ah + go * lda + eo);
        cp16(sb + PLANE + so,     Al + go * lda + eo);
        cp16(sb + 2 * PLANE + so, Bh + go * ldb + eo);
        cp16(sb + 3 * PLANE + so, Bl + go * ldb + eo);
    }
}

// ---------------- slab compute: 2 k16-steps x 3 split terms ----------------
__device__ __forceinline__ void compute_slab(uint32_t sb, float acc[4][4][4])
{
    const int lane = threadIdx.x & 31, wid = threadIdx.x >> 5;
    const int wm = wid >> 2, wn = wid & 3;
    const uint32_t aoff = (uint32_t)(wm * 64 + (lane & 15)) * 80 + (((lane >> 4) & 1) << 4);
    const uint32_t boff = (uint32_t)(wn * 32 + ((lane >> 4) & 1) * 8 + (lane & 7)) * 80
                        + (((lane >> 3) & 1) << 4);
#pragma unroll
    for (int kk = 0; kk < 2; ++kk) {
        const uint32_t ak = sb + aoff + kk * 32;
        const uint32_t bk = sb + 2 * PLANE + boff + kk * 32;
        uint32_t Ah[4][4], Al[4][4], Bh[2][4], Bl[2][4];
#pragma unroll
        for (int mi = 0; mi < 4; ++mi) ldsm4(Ah[mi], ak + mi * 1280);
#pragma unroll
        for (int p = 0; p < 2; ++p) ldsm4(Bh[p], bk + p * 1280);
#pragma unroll
        for (int mi = 0; mi < 4; ++mi)
#pragma unroll
            for (int ni = 0; ni < 4; ++ni)
                mma_bf16(acc[mi][ni], Ah[mi], &Bh[ni >> 1][(ni & 1) * 2]);
#pragma unroll
        for (int p = 0; p < 2; ++p) ldsm4(Bl[p], bk + PLANE + p * 1280);
#pragma unroll
        for (int mi = 0; mi < 4; ++mi)
#pragma unroll
            for (int ni = 0; ni < 4; ++ni)
                mma_bf16(acc[mi][ni], Ah[mi], &Bl[ni >> 1][(ni & 1) * 2]);
#pragma unroll
        for (int mi = 0; mi < 4; ++mi) ldsm4(Al[mi], ak + PLANE + mi * 1280);
#pragma unroll
        for (int mi = 0; mi < 4; ++mi)
#pragma unroll
            for (int ni = 0; ni < 4; ++ni)
                mma_bf16(acc[mi][ni], Al[mi], &Bh[ni >> 1][(ni & 1) * 2]);
    }
}

// ---------------- GEMM driver: acc[128x128] += split(A) @ split(B)^T ----------------
__device__ __forceinline__ void gemm_main(
    uint32_t smbase,
    const bf16* __restrict__ Ah, const bf16* __restrict__ Al, int lda,
    const bf16* __restrict__ Bh, const bf16* __restrict__ Bl, int ldb,
    int K, float acc[4][4][4])
{
    const int ns = K >> 5;
    issue_slab(smbase, Ah, Al, lda, Bh, Bl, ldb, 0);
    cp_commit();
    for (int s = 0; s < ns; ++s) {
        if (s + 1 < ns) {
            issue_slab(smbase + ((s + 1) & 1) * BUFSZ, Ah, Al, lda, Bh, Bl, ldb, (s + 1) * 32);
            cp_commit();
            cp_wait<1>();
        } else {
            cp_wait<0>();
        }
        __syncthreads();
        compute_slab(smbase + (s & 1) * BUFSZ, acc);
        __syncthreads();
    }
}

// Epilogue iteration: calls f(r_loc, c_loc, v0, v1) for each accum pair
template <typename F>
__device__ __forceinline__ void epilog_foreach(float acc[4][4][4], F f)
{
    const int lane = threadIdx.x & 31, wid = threadIdx.x >> 5;
    const int wm = wid >> 2, wn = wid & 3;
#pragma unroll
    for (int mi = 0; mi < 4; ++mi)
#pragma unroll
        for (int ni = 0; ni < 4; ++ni)
#pragma unroll
            for (int hf = 0; hf < 2; ++hf) {
                const int r_loc = wm * 64 + mi * 16 + (lane >> 2) + hf * 8;
                const int c_loc = wn * 32 + ni * 8 + (lane & 3) * 2;
                f(r_loc, c_loc, acc[mi][ni][hf * 2], acc[mi][ni][hf * 2 + 1]);
            }
}

// ---------------- conversion kernels ----------------
__global__ __launch_bounds__(256)
void k_split(const float* __restrict__ in, bf16* __restrict__ hp, bf16* __restrict__ lp, int n)
{
    for (int i = blockIdx.x * 256 + threadIdx.x; i < n; i += gridDim.x * 256)
        store_split1(hp + i, lp + i, in[i]);
}

// in [z][R][C] fp32 -> out [z][C][R] bf16 hi/lo
__global__ __launch_bounds__(256)
void k_tsplit(const float* __restrict__ in, bf16* __restrict__ hp, bf16* __restrict__ lp,
              int R, int C)
{
    __shared__ float tile[32][33];
    const int z = blockIdx.z;
    const int r0 = blockIdx.y * 32, c0 = blockIdx.x * 32;
    const int tx = threadIdx.x & 31, ty = threadIdx.x >> 5;   // 32 x 8
    const float* src = in + (size_t)z * R * C;
#pragma unroll
    for (int i = 0; i < 32; i += 8)
        tile[ty + i][tx] = src[(size_t)(r0 + ty + i) * C + c0 + tx];
    __syncthreads();
    bf16* hdst = hp + (size_t)z * R * C;
    bf16* ldst = lp + (size_t)z * R * C;
#pragma unroll
    for (int i = 0; i < 32; i += 8) {
        const float v = tile[tx][ty + i];
        const size_t o = (size_t)(c0 + ty + i) * R + r0 + tx;
        store_split1(hdst + o, ldst + o, v);
    }
}

// ---------------- block-wide sum (256 threads) ----------------
__device__ __forceinline__ float blockSum(float v)
{
    __shared__ float sh[9];
    const int lane = threadIdx.x & 31;
    const int w    = threadIdx.x >> 5;
#pragma unroll
    for (int o = 16; o > 0; o >>= 1) v += __shfl_down_sync(0xffffffffu, v, o);
    __syncthreads();
    if (lane == 0) sh[w] = v;
    __syncthreads();
    if (threadIdx.x == 0) {
        float s = 0.f;
#pragma unroll
        for (int i = 0; i < 8; ++i) s += sh[i];
        sh[8] = s;
    }
    __syncthreads();
    return sh[8];
}

// ---------------- kernel 1: latent = relu(x @ enc_h); rope -> QR ----------------
__global__ __launch_bounds__(256)
void k_latent()
{
    extern __shared__ char sm[];
    const uint32_t smb = smem_u32(sm);
    const int h = blockIdx.z;
    const int by = blockIdx.y, bx = blockIdx.x;
    float acc[4][4][4] = {};
    gemm_main(smb,
              g_xa_h + (size_t)by * 128 * DD,
              g_xa_l + (size_t)by * 128 * DD, DD,
              g_ep_h + ((size_t)h * NN + bx * 128) * DD,
              g_ep_l + ((size_t)h * NN + bx * 128) * DD, DD,
              DD, acc);

    epilog_foreach(acc, [&](int r_loc, int c_loc, float v0, float v1) {
        const int r = by * 128 + r_loc;
        const int b = r >> 11, t = r & 2047;
        const int n = bx * 128 + c_loc;          // even
        const size_t base = ((size_t)(b * NHH + h) * TT + t) * NN + n;
        const float e = fmaxf(v0, 0.f), o = fmaxf(v1, 0.f);
        *reinterpret_cast<float2*>(g_xs + base) = make_float2(e, o);
        const float freq = exp2f(-(float)n * 0.0625f) * INV2PI;
        const float ph = fmodf((float)t * freq, 1.0f) * TWOPI;
        float c, s;
        sincosf(ph, &s, &c);
        const float q0 = e * c - o * s, q1 = o * c + e * s;
        *reinterpret_cast<float2*>(g_qrf + base) = make_float2(q0, q1);
        store_split2(g_qr_h + base, g_qr_l + base, q0, q1);
    });
}

// ---------------- kernel 2a: diag score tiles = (QR_i QR_i^T) strict-lower ----------------
__global__ __launch_bounds__(256)
void k_diag()
{
    extern __shared__ char sm[];
    const uint32_t smb = smem_u32(sm);
    const int ch = blockIdx.x, bh = blockIdx.y;
    const bf16* Ah = g_qr_h + ((size_t)bh * TT + ch * 128) * NN;
    const bf16* Al = g_qr_l + ((size_t)bh * TT + ch * 128) * NN;
    float acc[4][4][4] = {};
    gemm_main(smb, Ah, Al, NN, Ah, Al, NN, NN, acc);

    bf16* oh = g_scd_h + ((size_t)(bh * NCH + ch)) * 128 * 128;
    bf16* ol = g_scd_l + ((size_t)(bh * NCH + ch)) * 128 * 128;
    epilog_foreach(acc, [&](int r_loc, int c_loc, float v0, float v1) {
        const size_t o = (size_t)r_loc * 128 + c_loc;
        store_split2(oh + o, ol + o,
                     (c_loc < r_loc) ? v0 : 0.f, (c_loc + 1 < r_loc) ? v1 : 0.f);
    });
}

// ---------------- kernel 2b: P_i[d][n] = x_i^T QR_i  (per bh, chunk) ----------------
__global__ __launch_bounds__(256)
void k_pout()
{
    extern __shared__ char sm[];
    const uint32_t smb = smem_u32(sm);
    const int nb = blockIdx.x;            // 0..1 (n tiles)
    const int db = blockIdx.y;            // 0..5 (d tiles)
    const int z  = blockIdx.z;            // bh*NCH + chunk
    const int bh = z / NCH, ch = z % NCH;
    const int b = bh / NHH;
    const int t0 = ch * 128;
    float acc[4][4][4] = {};
    gemm_main(smb,
              g_xt_h + ((size_t)b * DD + db * 128) * TT + t0,
              g_xt_l + ((size_t)b * DD + db * 128) * TT + t0, TT,
              g_qrt_h + ((size_t)bh * NN + nb * 128) * TT + t0,
              g_qrt_l + ((size_t)bh * NN + nb * 128) * TT + t0, TT,
              128, acc);

    float* out = g_pst + (size_t)z * DD * NN;
    epilog_foreach(acc, [&](int r_loc, int c_loc, float v0, float v1) {
        const int d = db * 128 + r_loc;
        const int n = nb * 128 + c_loc;
        *reinterpret_cast<float2*>(out + (size_t)d * NN + n) = make_float2(v0, v1);
    });
}

// ---------------- kernel 2c: exclusive prefix over chunks -> split states ----------------
__global__ __launch_bounds__(256)
void k_prefix()
{
    const int gid = blockIdx.x * 256 + threadIdx.x;   // bh * (DD*NN/2) threads
    const int n2 = gid & 127;                          // n/2
    const int d  = (gid >> 7) % DD;
    const int bh = gid / (128 * DD);
    if (bh >= BB * NHH) return;
    const size_t o0 = ((size_t)bh * NCH * DD + d) * NN + n2 * 2;
    const size_t istep = (size_t)DD * NN;
    float s0 = 0.f, s1 = 0.f;
#pragma unroll
    for (int i = 0; i < NCH; ++i) {
        const size_t o = o0 + (size_t)i * istep;
        store_split2(g_st_h + o, g_st_l + o, s0, s1);
        const float2 p = *reinterpret_cast<const float2*>(g_pst + o);
        s0 += p.x; s1 += p.y;
    }
}

// ---------------- kernel 3: yKV = diag_i @ x_i + QR_i @ S_i ----------------
__global__ __launch_bounds__(256)
void k_ykv2()
{
    extern __shared__ char sm[];
    const uint32_t smb = smem_u32(sm);
    const int nb = blockIdx.x;            // d tile 0..5
    const int ch = blockIdx.y;            // chunk
    const int bh = blockIdx.z;
    const int b = bh / NHH;
    const int t0 = ch * 128;
    float acc[4][4][4] = {};

    // intra-chunk: diag tile [t][s] @ x^T[d][s]
    gemm_main(smb,
              g_scd_h + ((size_t)(bh * NCH + ch)) * 128 * 128,
              g_scd_l + ((size_t)(bh * NCH + ch)) * 128 * 128, 128,
              g_xt_h + ((size_t)b * DD + nb * 128) * TT + t0,
              g_xt_l + ((size_t)b * DD + nb * 128) * TT + t0, TT,
              128, acc);
    // inter-chunk: QR_i[t][n] @ S_i[d][n]
    gemm_main(smb,
              g_qr_h + ((size_t)bh * TT + t0) * NN,
              g_qr_l + ((size_t)bh * TT + t0) * NN, NN,
              g_st_h + ((size_t)(bh * NCH + ch) * DD + nb * 128) * NN,
              g_st_l + ((size_t)(bh * NCH + ch) * DD + nb * 128) * NN, NN,
              NN, acc);

    epilog_foreach(acc, [&](int r_loc, int c_loc, float v0, float v1) {
        const int t = t0 + r_loc;
        const int d = nb * 128 + c_loc;
        *reinterpret_cast<float2*>(g_ykv + ((size_t)bh * TT + t) * DD + d) =
            make_float2(v0, v1);
    });
}

// ---------------- kernel 4: LN(yKV) -> bf16 planes ----------------
__global__ __launch_bounds__(256)
void k_ln_ykv()
{
    const size_t row = blockIdx.x;
    const float* p = g_ykv + row * DD;
    const int tid = threadIdx.x;
    float v[3];
    float sum = 0.f;
#pragma unroll
    for (int i = 0; i < 3; ++i) { v[i] = p[tid + 256 * i]; sum += v[i]; }
    const float m = blockSum(sum) * (1.0f / DD);
    float sq = 0.f;
#pragma unroll
    for (int i = 0; i < 3; ++i) { float d = v[i] - m; sq += d * d; }
    const float rstd = rsqrtf(blockSum(sq) * (1.0f / DD) + 1e-5f);
#pragma unroll
    for (int i = 0; i < 3; ++i) {
        const size_t o = row * DD + tid + 256 * i;
        store_split1(g_yn_h + o, g_yn_l + o, (v[i] - m) * rstd);
    }
}

// ---------------- kernel 5: y_sparse = relu(yn @ encv); xy = xs*ys ----------------
__global__ __launch_bounds__(256)
void k_ysparse(float* __restrict__ out_xy)
{
    extern __shared__ char sm[];
    const uint32_t smb = smem_u32(sm);
    const int nb = blockIdx.x, tb = blockIdx.y, bh = blockIdx.z;
    const int b = bh / NHH, h = bh % NHH;
    float acc[4][4][4] = {};
    gemm_main(smb,
              g_yn_h + ((size_t)bh * TT + tb * 128) * DD,
              g_yn_l + ((size_t)bh * TT + tb * 128) * DD, DD,
              g_evp_h + ((size_t)h * NN + nb * 128) * DD,
              g_evp_l + ((size_t)h * NN + nb * 128) * DD, DD,
              DD, acc);

    epilog_foreach(acc, [&](int r_loc, int c_loc, float v0, float v1) {
        const int t = tb * 128 + r_loc;
        const int n = nb * 128 + c_loc;
        const size_t sidx = ((size_t)bh * TT + t) * NN + n;
        const float2 xv = *reinterpret_cast<const float2*>(g_xs + sidx);
        const float xy0 = fmaxf(v0, 0.f) * xv.x;
        const float xy1 = fmaxf(v1, 0.f) * xv.y;
        *reinterpret_cast<float2*>(out_xy + sidx) = make_float2(xy0, xy1);
        const size_t fidx = ((size_t)(b * TT + t)) * KFLAT + h * NN + n;
        store_split2(g_fl_h + fidx, g_fl_l + fidx, xy0, xy1);
    });
}

// ---------------- kernel 6: yMLP = flat @ decoder ----------------
__global__ __launch_bounds__(256)
void k_ymlp()
{
    extern __shared__ char sm[];
    const uint32_t smb = smem_u32(sm);
    const int nb = blockIdx.x, by = blockIdx.y;
    float acc[4][4][4] = {};
    gemm_main(smb,
              g_fl_h + (size_t)by * 128 * KFLAT,
              g_fl_l + (size_t)by * 128 * KFLAT, KFLAT,
              g_dt_h + (size_t)nb * 128 * KFLAT,
              g_dt_l + (size_t)nb * 128 * KFLAT, KFLAT,
              KFLAT, acc);

    epilog_foreach(acc, [&](int r_loc, int c_loc, float v0, float v1) {
        const int r = by * 128 + r_loc;
        const int d = nb * 128 + c_loc;
        *reinterpret_cast<float2*>(g_ymlp + (size_t)r * DD + d) = make_float2(v0, v1);
    });
}

// ---------------- kernel 7: ln(yMLP)*sqrt(reg)*scale; out = ln(x+y) ----------------
__global__ __launch_bounds__(256)
void k_final(const float* __restrict__ x, const float* __restrict__ scale,
             const float* __restrict__ ract, float* __restrict__ out)
{
    const size_t r = blockIdx.x;
    const int tid = threadIdx.x;
    const float* yp = g_ymlp + r * DD;
    const float* xp = x + r * DD;

    float v[3];
    float sum = 0.f;
#pragma unroll
    for (int i = 0; i < 3; ++i) { v[i] = yp[tid + 256 * i]; sum += v[i]; }
    const float m1 = blockSum(sum) * (1.0f / DD);
    float sq = 0.f;
#pragma unroll
    for (int i = 0; i < 3; ++i) { float d = v[i] - m1; sq += d * d; }
    const float rs1 = rsqrtf(blockSum(sq) * (1.0f / DD) + 1e-5f);

    float z[3];
    float sum2 = 0.f;
#pragma unroll
    for (int i = 0; i < 3; ++i) {
        const int d = tid + 256 * i;
        float y = (v[i] - m1) * rs1;
        y *= sqrtf(0.1f / (ract[d] + 1e-6f)) * scale[d];
        z[i] = xp[d] + y;
        sum2 += z[i];
    }
    const float m2 = blockSum(sum2) * (1.0f / DD);
    float sq2 = 0.f;
#pragma unroll
    for (int i = 0; i < 3; ++i) { float d = z[i] - m2; sq2 += d * d; }
    const float rs2 = rsqrtf(blockSum(sq2) * (1.0f / DD) + 1e-5f);
#pragma unroll
    for (int i = 0; i < 3; ++i)
        out[r * DD + tid + 256 * i] = (z[i] - m2) * rs2;
}

// ---------------- launch ----------------
extern "C" void kernel_launch(void* const* d_in, const int* in_sizes, int n_in,
                              void* d_out, int out_size)
{
    const float* x     = (const float*)d_in[0];
    const float* enc   = (const float*)d_in[1];
    const float* encv  = (const float*)d_in[2];
    const float* dec   = (const float*)d_in[3];
    const float* scale = (const float*)d_in[4];
    const float* ract  = (const float*)d_in[5];

    float* out    = (float*)d_out;
    float* out_xy = out + (size_t)BB * TT * DD;

    static bool attr_done = false;
    if (!attr_done) {
        cudaFuncSetAttribute(k_latent,  cudaFuncAttributeMaxDynamicSharedMemorySize, SMEM_BYTES);
        cudaFuncSetAttribute(k_diag,    cudaFuncAttributeMaxDynamicSharedMemorySize, SMEM_BYTES);
        cudaFuncSetAttribute(k_pout,    cudaFuncAttributeMaxDynamicSharedMemorySize, SMEM_BYTES);
        cudaFuncSetAttribute(k_ykv2,    cudaFuncAttributeMaxDynamicSharedMemorySize, SMEM_BYTES);
        cudaFuncSetAttribute(k_ysparse, cudaFuncAttributeMaxDynamicSharedMemorySize, SMEM_BYTES);
        cudaFuncSetAttribute(k_ymlp,    cudaFuncAttributeMaxDynamicSharedMemorySize, SMEM_BYTES);
        attr_done = true;
    }

    float* qrf;
    bf16 *xa_h, *xa_l, *xt_h, *xt_l, *ep_h, *ep_l, *evp_h, *evp_l, *dt_h, *dt_l, *qrt_h, *qrt_l;
    cudaGetSymbolAddress((void**)&qrf,   g_qrf);
    cudaGetSymbolAddress((void**)&xa_h,  g_xa_h);  cudaGetSymbolAddress((void**)&xa_l,  g_xa_l);
    cudaGetSymbolAddress((void**)&xt_h,  g_xt_h);  cudaGetSymbolAddress((void**)&xt_l,  g_xt_l);
    cudaGetSymbolAddress((void**)&ep_h,  g_ep_h);  cudaGetSymbolAddress((void**)&ep_l,  g_ep_l);
    cudaGetSymbolAddress((void**)&evp_h, g_evp_h); cudaGetSymbolAddress((void**)&evp_l, g_evp_l);
    cudaGetSymbolAddress((void**)&dt_h,  g_dt_h);  cudaGetSymbolAddress((void**)&dt_l,  g_dt_l);
    cudaGetSymbolAddress((void**)&qrt_h, g_qrt_h); cudaGetSymbolAddress((void**)&qrt_l, g_qrt_l);

    // operand preparation
    k_split <<<4096, 256>>>(x, xa_h, xa_l, BB * TT * DD);
    k_tsplit<<<dim3(DD / 32, TT / 32, BB), 256>>>(x,    xt_h,  xt_l,  TT, DD);
    k_tsplit<<<dim3(NN / 32, DD / 32, NHH), 256>>>(enc,  ep_h,  ep_l,  DD, NN);
    k_tsplit<<<dim3(NN / 32, DD / 32, NHH), 256>>>(encv, evp_h, evp_l, DD, NN);
    k_tsplit<<<dim3(DD / 32, KFLAT / 32, 1), 256>>>(dec, dt_h,  dt_l,  KFLAT, DD);

    // pipeline
    k_latent <<<dim3(2, 32, NHH),       256, SMEM_BYTES>>>();
    k_tsplit <<<dim3(NN / 32, TT / 32, BB * NHH), 256>>>(qrf, qrt_h, qrt_l, TT, NN); // QR -> QR^T
    k_diag   <<<dim3(NCH, BB * NHH),    256, SMEM_BYTES>>>();
    k_pout   <<<dim3(2, 6, BB * NHH * NCH), 256, SMEM_BYTES>>>();
    k_prefix <<<(BB * NHH * DD * NN / 2 + 255) / 256, 256>>>();
    k_ykv2   <<<dim3(6, NCH, BB * NHH), 256, SMEM_BYTES>>>();
    k_ln_ykv <<<BB * NHH * TT, 256>>>();
    k_ysparse<<<dim3(2, 16, BB * NHH),  256, SMEM_BYTES>>>(out_xy);
    k_ymlp   <<<dim3(6, 32),            256, SMEM_BYTES>>>();
    k_final  <<<BB * TT, 256>>>(x, scale, ract, out);
}